// round 2
// baseline (speedup 1.0000x reference)
#include <cuda_runtime.h>

#define NV 262144            // 64*64*64
#define BIGF 1e9f

// scratch: [mask m (4)][bc (16)][voxel (NV)]  -> 67 MB
__device__ float g_f[64ull * NV];
__device__ float g_acc[64];

__global__ void k_zero() {
    if (threadIdx.x < 64) g_acc[threadIdx.x] = 0.0f;
}

__device__ __forceinline__ float warpsum(float v) {
#pragma unroll
    for (int o = 16; o > 0; o >>= 1) v += __shfl_xor_sync(0xffffffffu, v, o);
    return v;
}

// ---------------- softmax stats: tps/sumP/count per (b,c) + CE sum ----------------
__global__ void k_stats(const float* __restrict__ in, const int* __restrict__ tg) {
    float sP[8], tp[8], cn[8];
#pragma unroll
    for (int c = 0; c < 8; ++c) { sP[c] = 0.f; tp[c] = 0.f; cn[c] = 0.f; }
    float ce = 0.0f;
    int b = (int)((blockIdx.x * 1024u) >> 18);   // 1024 voxels per block, same batch
#pragma unroll 1
    for (int k = 0; k < 4; ++k) {
        unsigned idx = blockIdx.x * 1024u + k * 256u + threadIdx.x;  // < 524288
        unsigned v = idx & (NV - 1u);
        const float* p = in + (size_t)b * (8ull * NV) + v;
        float x[8];
#pragma unroll
        for (int c = 0; c < 8; ++c) x[c] = p[(size_t)c * NV];
        float m = x[0];
#pragma unroll
        for (int c = 1; c < 8; ++c) m = fmaxf(m, x[c]);
        float e[8]; float S = 0.f;
#pragma unroll
        for (int c = 0; c < 8; ++c) { e[c] = exp2f((x[c] - m) * 1.4426950408889634f); S += e[c]; }
        float r = 1.0f / S;
        int t = tg[idx];
        float xt = x[0];
#pragma unroll
        for (int c = 0; c < 8; ++c) {
            float pr = e[c] * r;
            sP[c] += pr;
            bool is = (c == t);
            tp[c] += is ? pr : 0.0f;
            cn[c] += is ? 1.0f : 0.0f;
            xt     = is ? x[c] : xt;
        }
        ce += (m - xt) + __log2f(S) * 0.69314718055994531f;
    }
#pragma unroll
    for (int c = 0; c < 8; ++c) {
        float a  = warpsum(tp[c]);
        float s2 = warpsum(sP[c]);
        float q  = warpsum(cn[c]);
        if ((threadIdx.x & 31) == 0) {
            atomicAdd(&g_acc[b * 8 + c], a);
            atomicAdd(&g_acc[16 + b * 8 + c], s2);
            atomicAdd(&g_acc[32 + b * 8 + c], q);
        }
    }
    float cs = warpsum(ce);
    if ((threadIdx.x & 31) == 0) atomicAdd(&g_acc[48], cs);
}

// ---------------- pass 1 (axis X): binary -> squared dist to nearest False ----------------
__device__ __forceinline__ float dt1(unsigned long long zeros, int x) {
    unsigned long long below = zeros << (63 - x);      // bits <= x
    int dfwd = below ? __clzll((long long)below) : 1000;
    unsigned long long above = zeros >> x;             // bits >= x
    int dbwd = above ? (__ffsll((long long)above) - 1) : 1000;
    int d = min(dfwd, dbwd);
    return (d > 63) ? BIGF : (float)(d * d);
}

__global__ void k_pass1(const float* __restrict__ in, const int* __restrict__ tg) {
    unsigned L = blockIdx.x * 256u + threadIdx.x;      // < 65536 lines (b,c,y,z)
    unsigned z = L & 63u, y = (L >> 6) & 63u;
    unsigned c = (L >> 12) & 7u, b = L >> 15;
    unsigned bc = b * 8u + c;
    const float* pin = in + (size_t)bc * NV + y * 64u + z;
    const int*   ptg = tg + (size_t)b  * NV + y * 64u + z;

    unsigned long long mP = 0ull, mT = 0ull;
#pragma unroll 4
    for (int x = 0; x < 64; ++x) {
        float v = pin[x * 4096];
        int   t = ptg[x * 4096];
        if (v > 0.5f)         mP |= 1ull << x;
        if ((unsigned)t == c) mT |= 1ull << x;
    }
    // mask order matches reference: 0=pred_fg, 1=tgt_fg, 2=pred_bg, 3=tgt_bg
    // zeros-of-mask: fg masks -> ~m ; bg masks -> m
    unsigned long long zFP = ~mP, zFT = ~mT, zBP = mP, zBT = mT;
    size_t off = y * 64u + z;
    float* o0 = g_f + (size_t)(0 * 16 + bc) * NV + off;
    float* o1 = g_f + (size_t)(1 * 16 + bc) * NV + off;
    float* o2 = g_f + (size_t)(2 * 16 + bc) * NV + off;
    float* o3 = g_f + (size_t)(3 * 16 + bc) * NV + off;
#pragma unroll 4
    for (int x = 0; x < 64; ++x) {
        o0[x * 4096] = dt1(zFP, x);
        o1[x * 4096] = dt1(zFT, x);
        o2[x * 4096] = dt1(zBP, x);
        o3[x * 4096] = dt1(zBT, x);
    }
}

// ---------------- min-plus core, length 64 (fully unrolled: (i-j)^2 are immediates) ----------------
__device__ __forceinline__ void minplus64(const float* __restrict__ fv, float* __restrict__ dout) {
#pragma unroll
    for (int it = 0; it < 4; ++it) {
        float d[16];
#pragma unroll
        for (int a = 0; a < 16; ++a) d[a] = 3.0e38f;
#pragma unroll
        for (int j = 0; j < 64; ++j) {
#pragma unroll
            for (int a = 0; a < 16; ++a) {
                const int i = it * 16 + a;
                const float q = (float)((i - j) * (i - j));
                d[a] = fminf(d[a], fv[j] + q);
            }
        }
#pragma unroll
        for (int a = 0; a < 16; ++a) dout[it * 16 + a] = d[a];
    }
}

// ---------------- pass 2 (axis Y, stride 64) ----------------
__global__ void __launch_bounds__(256) k_pass2() {
    unsigned L = blockIdx.x * 256u + threadIdx.x;      // < 262144 lines (vol,x,z)
    unsigned z = L & 63u, x = (L >> 6) & 63u, vol = L >> 12;
    float* f = g_f + (size_t)vol * NV + x * 4096u + z;
    float fv[64], d[64];
#pragma unroll
    for (int j = 0; j < 64; ++j) fv[j] = f[j * 64];
    minplus64(fv, d);
#pragma unroll
    for (int i = 0; i < 64; ++i) f[i * 64] = d[i];
}

// ---------------- pass 3 (axis Z, contiguous, vectorized) ----------------
__global__ void __launch_bounds__(256) k_pass3() {
    unsigned L = blockIdx.x * 256u + threadIdx.x;      // < 262144 lines (vol,x,y)
    unsigned y = L & 63u, x = (L >> 6) & 63u, vol = L >> 12;
    float* f = g_f + (size_t)vol * NV + x * 4096u + y * 64u;
    float fv[64], d[64];
    const float4* f4 = (const float4*)f;
#pragma unroll
    for (int j = 0; j < 16; ++j) {
        float4 t = f4[j];
        fv[4 * j + 0] = t.x; fv[4 * j + 1] = t.y; fv[4 * j + 2] = t.z; fv[4 * j + 3] = t.w;
    }
    minplus64(fv, d);
    float4* o4 = (float4*)f;
#pragma unroll
    for (int i = 0; i < 16; ++i) {
        float4 t;
        t.x = d[4 * i + 0]; t.y = d[4 * i + 1]; t.z = d[4 * i + 2]; t.w = d[4 * i + 3];
        o4[i] = t;
    }
}

// ---------------- min-plus over channel axis, length 8 ----------------
__device__ __forceinline__ void minplus8(const float* __restrict__ a, float* __restrict__ d) {
#pragma unroll
    for (int i = 0; i < 8; ++i) {
        float m = 3.0e38f;
#pragma unroll
        for (int j = 0; j < 8; ++j) {
            const float q = (float)((i - j) * (i - j));
            m = fminf(m, a[j] + q);
        }
        d[i] = m;
    }
}

// ---------------- HD reduction with fused channel-axis EDT pass ----------------
// The 4D EDT runs over (C,X,Y,Z); per-axis min-plus convolutions commute, so the
// C-axis pass (length 8) is applied here after the X/Y/Z passes, fused with the
// final weighted reduction.
__global__ void __launch_bounds__(256) k_hd(const float* __restrict__ in, const int* __restrict__ tg) {
    unsigned e = blockIdx.x * 256u + threadIdx.x;      // < 524288  (b, voxel)
    unsigned v = e & (NV - 1u);
    unsigned b = e >> 18;
    int t = tg[(size_t)b * NV + v];

    // load raw fields: a[mask][c]
    float a0[8], a1[8], a2[8], a3[8];
    const float* base = g_f + (size_t)b * (8ull * NV) + v;
#pragma unroll
    for (int c = 0; c < 8; ++c) {
        a0[c] = base[(size_t)(0 * 16) * NV + (size_t)c * NV];
        a1[c] = base[(size_t)(1 * 16) * NV + (size_t)c * NV];
        a2[c] = base[(size_t)(2 * 16) * NV + (size_t)c * NV];
        a3[c] = base[(size_t)(3 * 16) * NV + (size_t)c * NV];
    }
    float d0[8], d1[8], d2[8], d3[8];
    minplus8(a0, d0);
    minplus8(a1, d1);
    minplus8(a2, d2);
    minplus8(a3, d3);

    const float* pin = in + (size_t)b * (8ull * NV) + v;
    float acc = 0.0f;
#pragma unroll
    for (int c = 0; c < 8; ++c) {
        float xi = pin[(size_t)c * NV];
        float toh = (t == c) ? 1.0f : 0.0f;
        float pe = xi - toh; pe *= pe;
        // pdt = sqrt(d0)+sqrt(d2); pdt^2 = d0+d2+2*sqrt(d0*d2)
        float pdt2 = d0[c] + d2[c] + 2.0f * sqrtf(d0[c] * d2[c]);
        float tdt2 = d1[c] + d3[c] + 2.0f * sqrtf(d1[c] * d3[c]);
        acc += pe * (pdt2 + tdt2);
    }
    float s = warpsum(acc);
    if ((threadIdx.x & 31) == 0) atomicAdd(&g_acc[49], s);
}

// ---------------- finalize scalar ----------------
__global__ void k_final(float* out) {
    float diceAcc = 0.0f;
#pragma unroll
    for (int c = 1; c < 8; ++c) {
        float sb = 0.0f;
#pragma unroll
        for (int b = 0; b < 2; ++b) {
            float tps = g_acc[b * 8 + c];
            float sp  = g_acc[16 + b * 8 + c];
            float cnt = g_acc[32 + b * 8 + c];
            // alpha=beta=1: 2tps + fps + fns = sumP + count
            sb += 2.0f * tps / (sp + cnt + 1e-5f);
        }
        diceAcc += 0.5f * sb;
    }
    float dice = 1.0f - diceAcc * (1.0f / 7.0f);
    float ce = g_acc[48] * (1.0f / 524288.0f);
    float hd = g_acc[49] * (1.0f / 4194304.0f);
    out[0] = dice + ce + hd;
}

extern "C" void kernel_launch(void* const* d_in, const int* in_sizes, int n_in,
                              void* d_out, int out_size) {
    const float* in = (const float*)d_in[0];
    const int*   tg = (const int*)d_in[1];
    float* out = (float*)d_out;
    k_zero <<<1, 64>>>();
    k_stats<<<512, 256>>>(in, tg);
    k_pass1<<<256, 256>>>(in, tg);
    k_pass2<<<1024, 256>>>();
    k_pass3<<<1024, 256>>>();
    k_hd   <<<2048, 256>>>(in, tg);
    k_final<<<1, 1>>>(out);
}

// round 3
// speedup vs baseline: 1.3156x; 1.3156x over previous
#include <cuda_runtime.h>

#define NV 262144            // 64*64*64
#define BIGF 1e9f

// scratch: [mask m (4)][bc (16)][voxel (NV)]  -> 67 MB
__device__ float g_f[64ull * NV];
__device__ float g_acc[64];

__global__ void k_zero() {
    if (threadIdx.x < 64) g_acc[threadIdx.x] = 0.0f;
}

__device__ __forceinline__ float warpsum(float v) {
#pragma unroll
    for (int o = 16; o > 0; o >>= 1) v += __shfl_xor_sync(0xffffffffu, v, o);
    return v;
}

// ---------------- softmax stats: tps/sumP/count per (b,c) + CE sum ----------------
__global__ void k_stats(const float* __restrict__ in, const int* __restrict__ tg) {
    float sP[8], tp[8], cn[8];
#pragma unroll
    for (int c = 0; c < 8; ++c) { sP[c] = 0.f; tp[c] = 0.f; cn[c] = 0.f; }
    float ce = 0.0f;
    int b = (int)((blockIdx.x * 1024u) >> 18);   // 1024 voxels per block, same batch
#pragma unroll 1
    for (int k = 0; k < 4; ++k) {
        unsigned idx = blockIdx.x * 1024u + k * 256u + threadIdx.x;  // < 524288
        unsigned v = idx & (NV - 1u);
        const float* p = in + (size_t)b * (8ull * NV) + v;
        float x[8];
#pragma unroll
        for (int c = 0; c < 8; ++c) x[c] = p[(size_t)c * NV];
        float m = x[0];
#pragma unroll
        for (int c = 1; c < 8; ++c) m = fmaxf(m, x[c]);
        float e[8]; float S = 0.f;
#pragma unroll
        for (int c = 0; c < 8; ++c) { e[c] = exp2f((x[c] - m) * 1.4426950408889634f); S += e[c]; }
        float r = 1.0f / S;
        int t = tg[idx];
        float xt = x[0];
#pragma unroll
        for (int c = 0; c < 8; ++c) {
            float pr = e[c] * r;
            sP[c] += pr;
            bool is = (c == t);
            tp[c] += is ? pr : 0.0f;
            cn[c] += is ? 1.0f : 0.0f;
            xt     = is ? x[c] : xt;
        }
        ce += (m - xt) + __log2f(S) * 0.69314718055994531f;
    }
#pragma unroll
    for (int c = 0; c < 8; ++c) {
        float a  = warpsum(tp[c]);
        float s2 = warpsum(sP[c]);
        float q  = warpsum(cn[c]);
        if ((threadIdx.x & 31) == 0) {
            atomicAdd(&g_acc[b * 8 + c], a);
            atomicAdd(&g_acc[16 + b * 8 + c], s2);
            atomicAdd(&g_acc[32 + b * 8 + c], q);
        }
    }
    float cs = warpsum(ce);
    if ((threadIdx.x & 31) == 0) atomicAdd(&g_acc[48], cs);
}

// ---------------- pass 1 (axis X): binary -> squared dist to nearest False ----------------
__device__ __forceinline__ float dt1(unsigned long long zeros, int x) {
    unsigned long long below = zeros << (63 - x);      // bits <= x
    int dfwd = below ? __clzll((long long)below) : 1000;
    unsigned long long above = zeros >> x;             // bits >= x
    int dbwd = above ? (__ffsll((long long)above) - 1) : 1000;
    int d = min(dfwd, dbwd);
    return (d > 63) ? BIGF : (float)(d * d);
}

__global__ void k_pass1(const float* __restrict__ in, const int* __restrict__ tg) {
    unsigned L = blockIdx.x * 256u + threadIdx.x;      // < 65536 lines (b,c,y,z)
    unsigned z = L & 63u, y = (L >> 6) & 63u;
    unsigned c = (L >> 12) & 7u, b = L >> 15;
    unsigned bc = b * 8u + c;
    const float* pin = in + (size_t)bc * NV + y * 64u + z;
    const int*   ptg = tg + (size_t)b  * NV + y * 64u + z;

    unsigned long long mP = 0ull, mT = 0ull;
#pragma unroll 4
    for (int x = 0; x < 64; ++x) {
        float v = pin[x * 4096];
        int   t = ptg[x * 4096];
        if (v > 0.5f)         mP |= 1ull << x;
        if ((unsigned)t == c) mT |= 1ull << x;
    }
    // mask order matches reference: 0=pred_fg, 1=tgt_fg, 2=pred_bg, 3=tgt_bg
    unsigned long long zFP = ~mP, zFT = ~mT, zBP = mP, zBT = mT;
    size_t off = y * 64u + z;
    float* o0 = g_f + (size_t)(0 * 16 + bc) * NV + off;
    float* o1 = g_f + (size_t)(1 * 16 + bc) * NV + off;
    float* o2 = g_f + (size_t)(2 * 16 + bc) * NV + off;
    float* o3 = g_f + (size_t)(3 * 16 + bc) * NV + off;
#pragma unroll 4
    for (int x = 0; x < 64; ++x) {
        o0[x * 4096] = dt1(zFP, x);
        o1[x * 4096] = dt1(zFT, x);
        o2[x * 4096] = dt1(zBP, x);
        o3[x * 4096] = dt1(zBT, x);
    }
}

// ---------------- windowed min-plus, length 64, exact ----------------
// d(i) = min_j f(j)+(i-j)^2. Window |offsets| <= R around each 8-chunk; if the
// windowed min is <= (R+1)^2 it equals the full min (any outside j contributes
// >= (R+1)^2). Rare failures re-scan all j FROM GLOBAL MEMORY (so the register
// array fv is never dynamically indexed -> no local-memory spill).
#define RWIN 8
#define THRESH 81.0f   // (RWIN+1)^2

template <int STRIDE>
__device__ __forceinline__ void minplus64_win(const float* __restrict__ gptr,
                                              const float* __restrict__ fv,
                                              float* __restrict__ dout) {
#pragma unroll
    for (int c0 = 0; c0 < 64; c0 += 8) {
        const int jlo = (c0 - RWIN < 0) ? 0 : c0 - RWIN;
        const int jhi = (c0 + 7 + RWIN > 63) ? 63 : c0 + 7 + RWIN;
        float d[8];
#pragma unroll
        for (int a = 0; a < 8; ++a) d[a] = 3.0e38f;
#pragma unroll
        for (int j = jlo; j <= jhi; ++j) {
#pragma unroll
            for (int a = 0; a < 8; ++a) {
                const int i = c0 + a;
                const float q = (float)((i - j) * (i - j));
                d[a] = fminf(d[a], fv[j] + q);
            }
        }
        float mx = d[0];
#pragma unroll
        for (int a = 1; a < 8; ++a) mx = fmaxf(mx, d[a]);
        if (mx > THRESH) {
            // exact fallback: full scan, reload f(j) from gmem (dynamic j)
#pragma unroll 1
            for (int j = 0; j < 64; ++j) {
                float fj = gptr[j * STRIDE];
#pragma unroll
                for (int a = 0; a < 8; ++a) {
                    int dd = c0 + a - j;
                    d[a] = fminf(d[a], fj + (float)(dd * dd));
                }
            }
        }
#pragma unroll
        for (int a = 0; a < 8; ++a) dout[c0 + a] = d[a];
    }
}

// ---------------- pass 2 (axis Y, stride 64) ----------------
__global__ void __launch_bounds__(256, 3) k_pass2() {
    unsigned L = blockIdx.x * 256u + threadIdx.x;      // < 262144 lines (vol,x,z)
    unsigned z = L & 63u, x = (L >> 6) & 63u, vol = L >> 12;
    float* f = g_f + (size_t)vol * NV + x * 4096u + z;
    float fv[64], d[64];
#pragma unroll
    for (int j = 0; j < 64; ++j) fv[j] = f[j * 64];
    minplus64_win<64>(f, fv, d);
#pragma unroll
    for (int i = 0; i < 64; ++i) f[i * 64] = d[i];
}

// ---------------- pass 3 (axis Z, contiguous, vectorized) ----------------
__global__ void __launch_bounds__(256, 3) k_pass3() {
    unsigned L = blockIdx.x * 256u + threadIdx.x;      // < 262144 lines (vol,x,y)
    unsigned y = L & 63u, x = (L >> 6) & 63u, vol = L >> 12;
    float* f = g_f + (size_t)vol * NV + x * 4096u + y * 64u;
    float fv[64], d[64];
    const float4* f4 = (const float4*)f;
#pragma unroll
    for (int j = 0; j < 16; ++j) {
        float4 t = f4[j];
        fv[4 * j + 0] = t.x; fv[4 * j + 1] = t.y; fv[4 * j + 2] = t.z; fv[4 * j + 3] = t.w;
    }
    minplus64_win<1>(f, fv, d);
    float4* o4 = (float4*)f;
#pragma unroll
    for (int i = 0; i < 16; ++i) {
        float4 t;
        t.x = d[4 * i + 0]; t.y = d[4 * i + 1]; t.z = d[4 * i + 2]; t.w = d[4 * i + 3];
        o4[i] = t;
    }
}

// ---------------- min-plus over channel axis, length 8 ----------------
__device__ __forceinline__ void minplus8(const float* __restrict__ a, float* __restrict__ d) {
#pragma unroll
    for (int i = 0; i < 8; ++i) {
        float m = 3.0e38f;
#pragma unroll
        for (int j = 0; j < 8; ++j) {
            const float q = (float)((i - j) * (i - j));
            m = fminf(m, a[j] + q);
        }
        d[i] = m;
    }
}

// ---------------- HD reduction with fused channel-axis EDT pass ----------------
__global__ void __launch_bounds__(256) k_hd(const float* __restrict__ in, const int* __restrict__ tg) {
    unsigned e = blockIdx.x * 256u + threadIdx.x;      // < 524288  (b, voxel)
    unsigned v = e & (NV - 1u);
    unsigned b = e >> 18;
    int t = tg[(size_t)b * NV + v];

    float a0[8], a1[8], a2[8], a3[8];
    const float* base = g_f + (size_t)b * (8ull * NV) + v;
#pragma unroll
    for (int c = 0; c < 8; ++c) {
        a0[c] = base[(size_t)(0 * 16) * NV + (size_t)c * NV];
        a1[c] = base[(size_t)(1 * 16) * NV + (size_t)c * NV];
        a2[c] = base[(size_t)(2 * 16) * NV + (size_t)c * NV];
        a3[c] = base[(size_t)(3 * 16) * NV + (size_t)c * NV];
    }
    float d0[8], d1[8], d2[8], d3[8];
    minplus8(a0, d0);
    minplus8(a1, d1);
    minplus8(a2, d2);
    minplus8(a3, d3);

    const float* pin = in + (size_t)b * (8ull * NV) + v;
    float acc = 0.0f;
#pragma unroll
    for (int c = 0; c < 8; ++c) {
        float xi = pin[(size_t)c * NV];
        float toh = (t == c) ? 1.0f : 0.0f;
        float pe = xi - toh; pe *= pe;
        float pdt2 = d0[c] + d2[c] + 2.0f * sqrtf(d0[c] * d2[c]);
        float tdt2 = d1[c] + d3[c] + 2.0f * sqrtf(d1[c] * d3[c]);
        acc += pe * (pdt2 + tdt2);
    }
    float s = warpsum(acc);
    if ((threadIdx.x & 31) == 0) atomicAdd(&g_acc[49], s);
}

// ---------------- finalize scalar ----------------
__global__ void k_final(float* out) {
    float diceAcc = 0.0f;
#pragma unroll
    for (int c = 1; c < 8; ++c) {
        float sb = 0.0f;
#pragma unroll
        for (int b = 0; b < 2; ++b) {
            float tps = g_acc[b * 8 + c];
            float sp  = g_acc[16 + b * 8 + c];
            float cnt = g_acc[32 + b * 8 + c];
            sb += 2.0f * tps / (sp + cnt + 1e-5f);
        }
        diceAcc += 0.5f * sb;
    }
    float dice = 1.0f - diceAcc * (1.0f / 7.0f);
    float ce = g_acc[48] * (1.0f / 524288.0f);
    float hd = g_acc[49] * (1.0f / 4194304.0f);
    out[0] = dice + ce + hd;
}

extern "C" void kernel_launch(void* const* d_in, const int* in_sizes, int n_in,
                              void* d_out, int out_size) {
    const float* in = (const float*)d_in[0];
    const int*   tg = (const int*)d_in[1];
    float* out = (float*)d_out;
    k_zero <<<1, 64>>>();
    k_stats<<<512, 256>>>(in, tg);
    k_pass1<<<256, 256>>>(in, tg);
    k_pass2<<<1024, 256>>>();
    k_pass3<<<1024, 256>>>();
    k_hd   <<<2048, 256>>>(in, tg);
    k_final<<<1, 1>>>(out);
}

// round 4
// speedup vs baseline: 1.7310x; 1.3158x over previous
#include <cuda_runtime.h>

#define NV 262144            // 64*64*64
#define BIGF 1e9f

// scratch: [mask m (4)][bc (16)][voxel (NV)]  -> 67 MB
__device__ float g_f[64ull * NV];
__device__ float g_acc[64];

__global__ void k_zero() {
    if (threadIdx.x < 64) g_acc[threadIdx.x] = 0.0f;
}

__device__ __forceinline__ float warpsum(float v) {
#pragma unroll
    for (int o = 16; o > 0; o >>= 1) v += __shfl_xor_sync(0xffffffffu, v, o);
    return v;
}

// ---------------- softmax stats: tps/sumP/count per (b,c) + CE sum ----------------
__global__ void k_stats(const float* __restrict__ in, const int* __restrict__ tg) {
    float sP[8], tp[8], cn[8];
#pragma unroll
    for (int c = 0; c < 8; ++c) { sP[c] = 0.f; tp[c] = 0.f; cn[c] = 0.f; }
    float ce = 0.0f;
    int b = (int)((blockIdx.x * 1024u) >> 18);   // 1024 voxels per block, same batch
#pragma unroll 1
    for (int k = 0; k < 4; ++k) {
        unsigned idx = blockIdx.x * 1024u + k * 256u + threadIdx.x;  // < 524288
        unsigned v = idx & (NV - 1u);
        const float* p = in + (size_t)b * (8ull * NV) + v;
        float x[8];
#pragma unroll
        for (int c = 0; c < 8; ++c) x[c] = p[(size_t)c * NV];
        float m = x[0];
#pragma unroll
        for (int c = 1; c < 8; ++c) m = fmaxf(m, x[c]);
        float e[8]; float S = 0.f;
#pragma unroll
        for (int c = 0; c < 8; ++c) { e[c] = exp2f((x[c] - m) * 1.4426950408889634f); S += e[c]; }
        float r = 1.0f / S;
        int t = tg[idx];
        float xt = x[0];
#pragma unroll
        for (int c = 0; c < 8; ++c) {
            float pr = e[c] * r;
            sP[c] += pr;
            bool is = (c == t);
            tp[c] += is ? pr : 0.0f;
            cn[c] += is ? 1.0f : 0.0f;
            xt     = is ? x[c] : xt;
        }
        ce += (m - xt) + __log2f(S) * 0.69314718055994531f;
    }
#pragma unroll
    for (int c = 0; c < 8; ++c) {
        float a  = warpsum(tp[c]);
        float s2 = warpsum(sP[c]);
        float q  = warpsum(cn[c]);
        if ((threadIdx.x & 31) == 0) {
            atomicAdd(&g_acc[b * 8 + c], a);
            atomicAdd(&g_acc[16 + b * 8 + c], s2);
            atomicAdd(&g_acc[32 + b * 8 + c], q);
        }
    }
    float cs = warpsum(ce);
    if ((threadIdx.x & 31) == 0) atomicAdd(&g_acc[48], cs);
}

// ---------------- pass 1 (axis X): binary -> squared dist to nearest False ----------------
__device__ __forceinline__ float dt1(unsigned long long zeros, int x) {
    unsigned long long below = zeros << (63 - x);      // bits <= x
    int dfwd = below ? __clzll((long long)below) : 1000;
    unsigned long long above = zeros >> x;             // bits >= x
    int dbwd = above ? (__ffsll((long long)above) - 1) : 1000;
    int d = min(dfwd, dbwd);
    return (d > 63) ? BIGF : (float)(d * d);
}

__global__ void k_pass1(const float* __restrict__ in, const int* __restrict__ tg) {
    unsigned L = blockIdx.x * 256u + threadIdx.x;      // < 65536 lines (b,c,y,z)
    unsigned z = L & 63u, y = (L >> 6) & 63u;
    unsigned c = (L >> 12) & 7u, b = L >> 15;
    unsigned bc = b * 8u + c;
    const float* pin = in + (size_t)bc * NV + y * 64u + z;
    const int*   ptg = tg + (size_t)b  * NV + y * 64u + z;

    unsigned long long mP = 0ull, mT = 0ull;
#pragma unroll 4
    for (int x = 0; x < 64; ++x) {
        float v = pin[x * 4096];
        int   t = ptg[x * 4096];
        if (v > 0.5f)         mP |= 1ull << x;
        if ((unsigned)t == c) mT |= 1ull << x;
    }
    // mask order matches reference: 0=pred_fg, 1=tgt_fg, 2=pred_bg, 3=tgt_bg
    unsigned long long zFP = ~mP, zFT = ~mT, zBP = mP, zBT = mT;
    size_t off = y * 64u + z;
    float* o0 = g_f + (size_t)(0 * 16 + bc) * NV + off;
    float* o1 = g_f + (size_t)(1 * 16 + bc) * NV + off;
    float* o2 = g_f + (size_t)(2 * 16 + bc) * NV + off;
    float* o3 = g_f + (size_t)(3 * 16 + bc) * NV + off;
#pragma unroll 4
    for (int x = 0; x < 64; ++x) {
        o0[x * 4096] = dt1(zFP, x);
        o1[x * 4096] = dt1(zFT, x);
        o2[x * 4096] = dt1(zBP, x);
        o3[x * 4096] = dt1(zBT, x);
    }
}

// ---------------- fused Y+Z min-plus over one (y,z) plane in smem ----------------
// Exact: windowed min with |i-j|<=9 pruning (pairs with off^2>81 cannot beat the
// 81 threshold; if windowed min > 81 the full-scan fallback recomputes exactly).
template<int LSTRIDE, int LANESTRIDE>
__device__ __forceinline__ void pass_line(float* s, int t) {
    int lane = t & 63;           // orthogonal coordinate
    int h = t >> 6;              // 0..3 -> outputs i in [16h, 16h+16)
    float* bp = s + lane * LANESTRIDE;
    int jbase = 16 * h - 8;
    float fv[32];
#pragma unroll
    for (int k = 0; k < 32; ++k) {
        int j = jbase + k;
        fv[k] = (j >= 0 && j < 64) ? bp[j * LSTRIDE] : 3.0e38f;
    }
    float d[16];
#pragma unroll
    for (int a = 0; a < 16; ++a) d[a] = 3.0e38f;
    // chunk A: a=0..7 (i=16h+a), k=0..23, off = a+8-k
#pragma unroll
    for (int k = 0; k < 24; ++k) {
#pragma unroll
        for (int a = 0; a < 8; ++a) {
            const int off = a + 8 - k;
            if (off * off <= 81) d[a] = fminf(d[a], fv[k] + (float)(off * off));
        }
    }
    // chunk B: a=8..15, k=8..31, off = a+8-k
#pragma unroll
    for (int k = 8; k < 32; ++k) {
#pragma unroll
        for (int a = 8; a < 16; ++a) {
            const int off = a + 8 - k;
            if (off * off <= 81) d[a] = fminf(d[a], fv[k] + (float)(off * off));
        }
    }
    float mxA = d[0], mxB = d[8];
#pragma unroll
    for (int a = 1; a < 8; ++a) { mxA = fmaxf(mxA, d[a]); mxB = fmaxf(mxB, d[a + 8]); }
    if (mxA > 81.0f) {
#pragma unroll 1
        for (int j = 0; j < 64; ++j) {
            float fj = bp[j * LSTRIDE];
#pragma unroll
            for (int a = 0; a < 8; ++a) { int dd = 16 * h + a - j; d[a] = fminf(d[a], fj + (float)(dd * dd)); }
        }
    }
    if (mxB > 81.0f) {
#pragma unroll 1
        for (int j = 0; j < 64; ++j) {
            float fj = bp[j * LSTRIDE];
#pragma unroll
            for (int a = 8; a < 16; ++a) { int dd = 16 * h + a - j; d[a] = fminf(d[a], fj + (float)(dd * dd)); }
        }
    }
    __syncthreads();   // all reads (incl. fallback) done before anyone writes
#pragma unroll
    for (int a = 0; a < 16; ++a) bp[(16 * h + a) * LSTRIDE] = d[a];
    __syncthreads();
}

__global__ void __launch_bounds__(256) k_pass23() {
    __shared__ float s[64 * 65];
    unsigned vol = blockIdx.x >> 6, x = blockIdx.x & 63u;
    float* g = g_f + (size_t)vol * NV + x * 4096u;   // contiguous (y,z) plane
    int t = threadIdx.x;
    // load plane (float4, coalesced) into padded smem
    {
        const float4* g4 = (const float4*)g;
#pragma unroll
        for (int m = 0; m < 4; ++m) {
            int e4 = m * 256 + t;            // 1024 float4s
            float4 val = g4[e4];
            int e = e4 * 4;
            int y = e >> 6, z = e & 63;
            float* sp = s + y * 65 + z;
            sp[0] = val.x; sp[1] = val.y; sp[2] = val.z; sp[3] = val.w;
        }
    }
    __syncthreads();
    // Y pass: line along y (smem stride 65), lane = z (stride 1)
    pass_line<65, 1>(s, t);
    // Z pass: line along z (stride 1), lane = y (stride 65)
    pass_line<1, 65>(s, t);
    // store plane
    {
        float4* g4 = (float4*)g;
#pragma unroll
        for (int m = 0; m < 4; ++m) {
            int e4 = m * 256 + t;
            int e = e4 * 4;
            int y = e >> 6, z = e & 63;
            const float* sp = s + y * 65 + z;
            float4 val;
            val.x = sp[0]; val.y = sp[1]; val.z = sp[2]; val.w = sp[3];
            g4[e4] = val;
        }
    }
}

// ---------------- min-plus over channel axis, length 8 ----------------
__device__ __forceinline__ void minplus8(const float* __restrict__ a, float* __restrict__ d) {
#pragma unroll
    for (int i = 0; i < 8; ++i) {
        float m = 3.0e38f;
#pragma unroll
        for (int j = 0; j < 8; ++j) {
            const float q = (float)((i - j) * (i - j));
            m = fminf(m, a[j] + q);
        }
        d[i] = m;
    }
}

// ---------------- HD reduction with fused channel-axis EDT pass ----------------
// pred_dt = sqrt(d_fg)+sqrt(d_bg); one of the two is exactly 0 at every voxel
// (a voxel is a False of fg or a False of bg), so pred_dt^2 = d_fg + d_bg.
__global__ void __launch_bounds__(256) k_hd(const float* __restrict__ in, const int* __restrict__ tg) {
    unsigned e = blockIdx.x * 256u + threadIdx.x;      // < 524288  (b, voxel)
    unsigned v = e & (NV - 1u);
    unsigned b = e >> 18;
    int t = tg[(size_t)b * NV + v];

    float a0[8], a1[8], a2[8], a3[8];
    const float* base = g_f + (size_t)b * (8ull * NV) + v;
#pragma unroll
    for (int c = 0; c < 8; ++c) {
        a0[c] = base[(size_t)(0 * 16) * NV + (size_t)c * NV];
        a1[c] = base[(size_t)(1 * 16) * NV + (size_t)c * NV];
        a2[c] = base[(size_t)(2 * 16) * NV + (size_t)c * NV];
        a3[c] = base[(size_t)(3 * 16) * NV + (size_t)c * NV];
    }
    float d0[8], d1[8], d2[8], d3[8];
    minplus8(a0, d0);
    minplus8(a1, d1);
    minplus8(a2, d2);
    minplus8(a3, d3);

    const float* pin = in + (size_t)b * (8ull * NV) + v;
    float acc = 0.0f;
#pragma unroll
    for (int c = 0; c < 8; ++c) {
        float xi = pin[(size_t)c * NV];
        float toh = (t == c) ? 1.0f : 0.0f;
        float pe = xi - toh; pe *= pe;
        acc += pe * (d0[c] + d2[c] + d1[c] + d3[c]);
    }
    float s = warpsum(acc);
    if ((threadIdx.x & 31) == 0) atomicAdd(&g_acc[49], s);
}

// ---------------- finalize scalar ----------------
__global__ void k_final(float* out) {
    float diceAcc = 0.0f;
#pragma unroll
    for (int c = 1; c < 8; ++c) {
        float sb = 0.0f;
#pragma unroll
        for (int b = 0; b < 2; ++b) {
            float tps = g_acc[b * 8 + c];
            float sp  = g_acc[16 + b * 8 + c];
            float cnt = g_acc[32 + b * 8 + c];
            sb += 2.0f * tps / (sp + cnt + 1e-5f);
        }
        diceAcc += 0.5f * sb;
    }
    float dice = 1.0f - diceAcc * (1.0f / 7.0f);
    float ce = g_acc[48] * (1.0f / 524288.0f);
    float hd = g_acc[49] * (1.0f / 4194304.0f);
    out[0] = dice + ce + hd;
}

extern "C" void kernel_launch(void* const* d_in, const int* in_sizes, int n_in,
                              void* d_out, int out_size) {
    const float* in = (const float*)d_in[0];
    const int*   tg = (const int*)d_in[1];
    float* out = (float*)d_out;
    k_zero  <<<1, 64>>>();
    k_stats <<<512, 256>>>(in, tg);
    k_pass1 <<<256, 256>>>(in, tg);
    k_pass23<<<4096, 256>>>();
    k_hd    <<<2048, 256>>>(in, tg);
    k_final <<<1, 1>>>(out);
}

// round 5
// speedup vs baseline: 1.9475x; 1.1250x over previous
#include <cuda_runtime.h>

#define NV 262144            // 64*64*64
#define BIGF 1e9f

// scratch: [mask m (4)][bc (16)][voxel (NV)]  -> 67 MB
__device__ float g_f[64ull * NV];
__device__ float g_acc[64];
__device__ unsigned g_cnt;

__device__ __forceinline__ float warpsum(float v) {
#pragma unroll
    for (int o = 16; o > 0; o >>= 1) v += __shfl_xor_sync(0xffffffffu, v, o);
    return v;
}

// ---------------- pass 1 (axis X): binary -> squared dist to nearest False ----------------
__device__ __forceinline__ float dt1(unsigned long long zeros, int x) {
    unsigned long long below = zeros << (63 - x);      // bits <= x
    int dfwd = below ? __clzll((long long)below) : 1000;
    unsigned long long above = zeros >> x;             // bits >= x
    int dbwd = above ? (__ffsll((long long)above) - 1) : 1000;
    int d = min(dfwd, dbwd);
    return (d > 63) ? BIGF : (float)(d * d);
}

__global__ void k_pass1(const float* __restrict__ in, const int* __restrict__ tg) {
    if (blockIdx.x == 0) {       // reset accumulators for this replay
        if (threadIdx.x < 64) g_acc[threadIdx.x] = 0.0f;
        if (threadIdx.x == 64) g_cnt = 0u;
    }
    unsigned L = blockIdx.x * 256u + threadIdx.x;      // < 65536 lines (b,c,y,z)
    unsigned z = L & 63u, y = (L >> 6) & 63u;
    unsigned c = (L >> 12) & 7u, b = L >> 15;
    unsigned bc = b * 8u + c;
    const float* pin = in + (size_t)bc * NV + y * 64u + z;
    const int*   ptg = tg + (size_t)b  * NV + y * 64u + z;

    unsigned long long mP = 0ull, mT = 0ull;
#pragma unroll 4
    for (int x = 0; x < 64; ++x) {
        float v = pin[x * 4096];
        int   t = ptg[x * 4096];
        if (v > 0.5f)         mP |= 1ull << x;
        if ((unsigned)t == c) mT |= 1ull << x;
    }
    // mask order: 0=pred_fg, 1=tgt_fg, 2=pred_bg, 3=tgt_bg
    unsigned long long zFP = ~mP, zFT = ~mT, zBP = mP, zBT = mT;
    size_t off = y * 64u + z;
    float* o0 = g_f + (size_t)(0 * 16 + bc) * NV + off;
    float* o1 = g_f + (size_t)(1 * 16 + bc) * NV + off;
    float* o2 = g_f + (size_t)(2 * 16 + bc) * NV + off;
    float* o3 = g_f + (size_t)(3 * 16 + bc) * NV + off;
#pragma unroll 4
    for (int x = 0; x < 64; ++x) {
        o0[x * 4096] = dt1(zFP, x);
        o1[x * 4096] = dt1(zFT, x);
        o2[x * 4096] = dt1(zBP, x);
        o3[x * 4096] = dt1(zBT, x);
    }
}

// ---------------- fused Y+Z min-plus over one (y,z) plane in smem ----------------
// Exact: windowed min, pairs |i-j|<=5 (off^2<=25). If windowed min <= 36 it is
// the true min (outside pairs contribute >= 36); otherwise full-scan fallback.
template<int LSTRIDE, int LANESTRIDE>
__device__ __forceinline__ void pass_line(float* s, int t) {
    int lane = t & 63;           // orthogonal coordinate
    int h = t >> 6;              // 0..3 -> outputs i in [16h, 16h+16)
    float* bp = s + lane * LANESTRIDE;
    int jbase = 16 * h - 5;
    float fv[26];
#pragma unroll
    for (int k = 0; k < 26; ++k) {
        int j = jbase + k;
        fv[k] = (j >= 0 && j < 64) ? bp[j * LSTRIDE] : 3.0e38f;
    }
    float d[16];
#pragma unroll
    for (int a = 0; a < 16; ++a) d[a] = 3.0e38f;
    // chunk A: a=0..7 (i=16h+a), off = a+5-k
#pragma unroll
    for (int k = 0; k < 18; ++k) {
#pragma unroll
        for (int a = 0; a < 8; ++a) {
            const int off = a + 5 - k;
            if (off * off <= 25) d[a] = fminf(d[a], fv[k] + (float)(off * off));
        }
    }
    // chunk B: a=8..15
#pragma unroll
    for (int k = 8; k < 26; ++k) {
#pragma unroll
        for (int a = 8; a < 16; ++a) {
            const int off = a + 5 - k;
            if (off * off <= 25) d[a] = fminf(d[a], fv[k] + (float)(off * off));
        }
    }
    float mxA = d[0], mxB = d[8];
#pragma unroll
    for (int a = 1; a < 8; ++a) { mxA = fmaxf(mxA, d[a]); mxB = fmaxf(mxB, d[a + 8]); }
    if (mxA > 36.0f) {
#pragma unroll 1
        for (int j = 0; j < 64; ++j) {
            float fj = bp[j * LSTRIDE];
#pragma unroll
            for (int a = 0; a < 8; ++a) { int dd = 16 * h + a - j; d[a] = fminf(d[a], fj + (float)(dd * dd)); }
        }
    }
    if (mxB > 36.0f) {
#pragma unroll 1
        for (int j = 0; j < 64; ++j) {
            float fj = bp[j * LSTRIDE];
#pragma unroll
            for (int a = 8; a < 16; ++a) { int dd = 16 * h + a - j; d[a] = fminf(d[a], fj + (float)(dd * dd)); }
        }
    }
    __syncthreads();   // all reads (incl. fallback) done before anyone writes
#pragma unroll
    for (int a = 0; a < 16; ++a) bp[(16 * h + a) * LSTRIDE] = d[a];
    __syncthreads();
}

__global__ void __launch_bounds__(256) k_pass23() {
    __shared__ float s[64 * 65];
    unsigned vol = blockIdx.x >> 6, x = blockIdx.x & 63u;
    float* g = g_f + (size_t)vol * NV + x * 4096u;   // contiguous (y,z) plane
    int t = threadIdx.x;
    {
        const float4* g4 = (const float4*)g;
#pragma unroll
        for (int m = 0; m < 4; ++m) {
            int e4 = m * 256 + t;            // 1024 float4s
            float4 val = g4[e4];
            int e = e4 * 4;
            int y = e >> 6, z = e & 63;
            float* sp = s + y * 65 + z;
            sp[0] = val.x; sp[1] = val.y; sp[2] = val.z; sp[3] = val.w;
        }
    }
    __syncthreads();
    pass_line<65, 1>(s, t);   // Y pass
    pass_line<1, 65>(s, t);   // Z pass
    {
        float4* g4 = (float4*)g;
#pragma unroll
        for (int m = 0; m < 4; ++m) {
            int e4 = m * 256 + t;
            int e = e4 * 4;
            int y = e >> 6, z = e & 63;
            const float* sp = s + y * 65 + z;
            float4 val;
            val.x = sp[0]; val.y = sp[1]; val.z = sp[2]; val.w = sp[3];
            g4[e4] = val;
        }
    }
}

// ---------------- windowed min-plus over channel axis, length 8, exact ----------------
__device__ __forceinline__ void minplus8w(const float* __restrict__ a, float* __restrict__ d) {
#pragma unroll
    for (int i = 0; i < 8; ++i) {
        float m = 3.0e38f;
#pragma unroll
        for (int j = 0; j < 8; ++j) {
            const int off = i - j;
            if (off * off <= 4) m = fminf(m, a[j] + (float)(off * off));
        }
        d[i] = m;
    }
    float mx = d[0];
#pragma unroll
    for (int i = 1; i < 8; ++i) mx = fmaxf(mx, d[i]);
    if (mx > 9.0f) {
#pragma unroll
        for (int i = 0; i < 8; ++i) {
            float m = d[i];
#pragma unroll
            for (int j = 0; j < 8; ++j) {
                const int off = i - j;
                m = fminf(m, a[j] + (float)(off * off));
            }
            d[i] = m;
        }
    }
}

// ---------------- fused stats + HD (+ channel EDT pass) + final ----------------
// 512 blocks x 256 threads x 4 voxels = 524288 (b, voxel) entries
__global__ void __launch_bounds__(256) k_shd(const float* __restrict__ in, const int* __restrict__ tg,
                                             float* __restrict__ out) {
    unsigned E = blockIdx.x * 1024u + threadIdx.x * 4u;
    unsigned v = E & (NV - 1u);
    unsigned b = E >> 18;

    float X[4][8];
#pragma unroll
    for (int c = 0; c < 8; ++c) {
        float4 t4 = *(const float4*)(in + (size_t)(b * 8 + c) * NV + v);
        X[0][c] = t4.x; X[1][c] = t4.y; X[2][c] = t4.z; X[3][c] = t4.w;
    }
    int T[4];
    { int4 tt = *(const int4*)(tg + (size_t)b * NV + v); T[0] = tt.x; T[1] = tt.y; T[2] = tt.z; T[3] = tt.w; }

    float tp[8], sP[8], cn[8];
#pragma unroll
    for (int c = 0; c < 8; ++c) { tp[c] = 0.f; sP[c] = 0.f; cn[c] = 0.f; }
    float ce = 0.0f, hd = 0.0f;

    // softmax stats per voxel component
#pragma unroll
    for (int k = 0; k < 4; ++k) {
        float m = X[k][0];
#pragma unroll
        for (int c = 1; c < 8; ++c) m = fmaxf(m, X[k][c]);
        float e[8]; float S = 0.f;
#pragma unroll
        for (int c = 0; c < 8; ++c) { e[c] = exp2f((X[k][c] - m) * 1.4426950408889634f); S += e[c]; }
        float r = 1.0f / S;
        int t = T[k];
        float xt = X[k][0];
#pragma unroll
        for (int c = 0; c < 8; ++c) {
            float pr = e[c] * r;
            sP[c] += pr;
            bool is = (c == t);
            tp[c] += is ? pr : 0.0f;
            cn[c] += is ? 1.0f : 0.0f;
            xt     = is ? X[k][c] : xt;
        }
        ce += (m - xt) + __log2f(S) * 0.69314718055994531f;
    }

    // HD: per mask, channel-axis min-plus then weighted accumulate.
    // pred_dt^2 = d_fg + d_bg exactly (one of the pair is 0 at every voxel).
#pragma unroll
    for (int mk = 0; mk < 4; ++mk) {
        float A[4][8];
#pragma unroll
        for (int c = 0; c < 8; ++c) {
            float4 t4 = *(const float4*)(g_f + (size_t)(mk * 16 + b * 8 + c) * NV + v);
            A[0][c] = t4.x; A[1][c] = t4.y; A[2][c] = t4.z; A[3][c] = t4.w;
        }
#pragma unroll
        for (int k = 0; k < 4; ++k) {
            float dch[8];
            minplus8w(A[k], dch);
            int t = T[k];
#pragma unroll
            for (int c = 0; c < 8; ++c) {
                float toh = (t == c) ? 1.0f : 0.0f;
                float pe = X[k][c] - toh;
                hd += pe * pe * dch[c];
            }
        }
    }

    // reduce 26 scalars per warp, lane-0 atomics
#pragma unroll
    for (int c = 0; c < 8; ++c) {
        float a  = warpsum(tp[c]);
        float s2 = warpsum(sP[c]);
        float q  = warpsum(cn[c]);
        if ((threadIdx.x & 31) == 0) {
            atomicAdd(&g_acc[b * 8 + c], a);
            atomicAdd(&g_acc[16 + b * 8 + c], s2);
            atomicAdd(&g_acc[32 + b * 8 + c], q);
        }
    }
    float cs = warpsum(ce);
    float hs = warpsum(hd);
    if ((threadIdx.x & 31) == 0) {
        atomicAdd(&g_acc[48], cs);
        atomicAdd(&g_acc[49], hs);
    }

    // last block finalizes (threadfence + completion counter)
    __threadfence();
    if (threadIdx.x == 0) {
        unsigned done = atomicAdd(&g_cnt, 1u);
        if (done == gridDim.x - 1) {
            __threadfence();
            float diceAcc = 0.0f;
#pragma unroll
            for (int c = 1; c < 8; ++c) {
                float sb = 0.0f;
#pragma unroll
                for (int bb = 0; bb < 2; ++bb) {
                    float tps = g_acc[bb * 8 + c];
                    float sp  = g_acc[16 + bb * 8 + c];
                    float cnt = g_acc[32 + bb * 8 + c];
                    sb += 2.0f * tps / (sp + cnt + 1e-5f);   // alpha=beta=1
                }
                diceAcc += 0.5f * sb;
            }
            float dice = 1.0f - diceAcc * (1.0f / 7.0f);
            float cef = g_acc[48] * (1.0f / 524288.0f);
            float hdf = g_acc[49] * (1.0f / 4194304.0f);
            out[0] = dice + cef + hdf;
        }
    }
}

extern "C" void kernel_launch(void* const* d_in, const int* in_sizes, int n_in,
                              void* d_out, int out_size) {
    const float* in = (const float*)d_in[0];
    const int*   tg = (const int*)d_in[1];
    float* out = (float*)d_out;
    k_pass1 <<<256, 256>>>(in, tg);
    k_pass23<<<4096, 256>>>();
    k_shd   <<<512, 256>>>(in, tg, out);
}

// round 6
// speedup vs baseline: 2.0428x; 1.0490x over previous
#include <cuda_runtime.h>

#define NV 262144            // 64*64*64
#define BIGF 1e9f

// scratch: [mask m (4)][bc (16)][voxel (NV)]  -> 67 MB
__device__ float g_f[64ull * NV];
__device__ float g_acc[64];
__device__ unsigned g_cnt;

__device__ __forceinline__ float warpsum(float v) {
#pragma unroll
    for (int o = 16; o > 0; o >>= 1) v += __shfl_xor_sync(0xffffffffu, v, o);
    return v;
}

// ---------------- pass 1 (axis X): binary -> squared dist to nearest False ----------------
__device__ __forceinline__ float dt1(unsigned long long zeros, int x) {
    unsigned long long below = zeros << (63 - x);      // bits <= x
    int dfwd = below ? __clzll((long long)below) : 1000;
    unsigned long long above = zeros >> x;             // bits >= x
    int dbwd = above ? (__ffsll((long long)above) - 1) : 1000;
    int d = min(dfwd, dbwd);
    return (d > 63) ? BIGF : (float)(d * d);
}

// 1024 blocks x 256 threads. Block = one (b,c,y) group of 64 z-lines.
// Each line is split over 4 threads (part = tid>>6): 16 loads each, partial
// masks combined via smem; then each part writes ONE mask's 64 outputs.
__global__ void __launch_bounds__(256) k_pass1(const float* __restrict__ in, const int* __restrict__ tg) {
    if (blockIdx.x == 0) {       // reset accumulators for this replay
        if (threadIdx.x < 64) g_acc[threadIdx.x] = 0.0f;
        if (threadIdx.x == 64) g_cnt = 0u;
    }
    unsigned g = blockIdx.x;                 // (b,c,y)
    unsigned y = g & 63u, c = (g >> 6) & 7u, b = g >> 9;
    unsigned bc = b * 8u + c;
    int t = threadIdx.x;
    int z = t & 63;
    int part = t >> 6;                       // 0..3
    const float* pin = in + (size_t)bc * NV + y * 64u + z;
    const int*   ptg = tg + (size_t)b  * NV + y * 64u + z;

    unsigned m16 = 0u;                       // low 16: pred, high 16: tgt
#pragma unroll
    for (int k = 0; k < 16; ++k) {
        int x = part * 16 + k;
        float v = pin[(size_t)x * 4096];
        int   tt = ptg[(size_t)x * 4096];
        if (v > 0.5f)          m16 |= 1u << k;
        if ((unsigned)tt == c) m16 |= 1u << (16 + k);
    }
    __shared__ unsigned sm[256];
    sm[t] = m16;
    __syncthreads();
    unsigned long long mP = 0ull, mT = 0ull;
#pragma unroll
    for (int p = 0; p < 4; ++p) {
        unsigned w = sm[z + p * 64];
        mP |= (unsigned long long)(w & 0xFFFFu) << (16 * p);
        mT |= (unsigned long long)(w >> 16)     << (16 * p);
    }
    // mask order: 0=pred_fg, 1=tgt_fg, 2=pred_bg, 3=tgt_bg ; zeros-of-mask
    unsigned long long zeros = (part == 0) ? ~mP : (part == 1) ? ~mT : (part == 2) ? mP : mT;
    float* o = g_f + (size_t)(part * 16 + bc) * NV + y * 64u + z;
#pragma unroll 4
    for (int x = 0; x < 64; ++x) o[(size_t)x * 4096] = dt1(zeros, x);
}

// ---------------- fused Y+Z min-plus over one (y,z) plane in smem ----------------
// Exact: windowed min, pairs |i-j|<=4 (off^2<=16). If windowed min <= 25 it is
// the true min (outside pairs contribute >= 25); otherwise full-scan fallback.
template<int LSTRIDE, int LANESTRIDE>
__device__ __forceinline__ void pass_line(float* s, int t) {
    int lane = t & 63;           // orthogonal coordinate
    int h = t >> 6;              // 0..3 -> outputs i in [16h, 16h+16)
    float* bp = s + lane * LANESTRIDE;
    int jbase = 16 * h - 4;
    float fv[24];
#pragma unroll
    for (int k = 0; k < 24; ++k) {
        int j = jbase + k;
        fv[k] = (j >= 0 && j < 64) ? bp[j * LSTRIDE] : 3.0e38f;
    }
    float d[16];
#pragma unroll
    for (int a = 0; a < 16; ++a) d[a] = 3.0e38f;
    // chunk A: a=0..7 (i=16h+a), off = a+4-k
#pragma unroll
    for (int k = 0; k < 16; ++k) {
#pragma unroll
        for (int a = 0; a < 8; ++a) {
            const int off = a + 4 - k;
            if (off * off <= 16) d[a] = fminf(d[a], fv[k] + (float)(off * off));
        }
    }
    // chunk B: a=8..15
#pragma unroll
    for (int k = 8; k < 24; ++k) {
#pragma unroll
        for (int a = 8; a < 16; ++a) {
            const int off = a + 4 - k;
            if (off * off <= 16) d[a] = fminf(d[a], fv[k] + (float)(off * off));
        }
    }
    float mxA = d[0], mxB = d[8];
#pragma unroll
    for (int a = 1; a < 8; ++a) { mxA = fmaxf(mxA, d[a]); mxB = fmaxf(mxB, d[a + 8]); }
    if (mxA > 25.0f) {
#pragma unroll 1
        for (int j = 0; j < 64; ++j) {
            float fj = bp[j * LSTRIDE];
#pragma unroll
            for (int a = 0; a < 8; ++a) { int dd = 16 * h + a - j; d[a] = fminf(d[a], fj + (float)(dd * dd)); }
        }
    }
    if (mxB > 25.0f) {
#pragma unroll 1
        for (int j = 0; j < 64; ++j) {
            float fj = bp[j * LSTRIDE];
#pragma unroll
            for (int a = 8; a < 16; ++a) { int dd = 16 * h + a - j; d[a] = fminf(d[a], fj + (float)(dd * dd)); }
        }
    }
    __syncthreads();   // all reads (incl. fallback) done before anyone writes
#pragma unroll
    for (int a = 0; a < 16; ++a) bp[(16 * h + a) * LSTRIDE] = d[a];
    __syncthreads();
}

__global__ void __launch_bounds__(256) k_pass23() {
    __shared__ float s[64 * 65];
    unsigned vol = blockIdx.x >> 6, x = blockIdx.x & 63u;
    float* g = g_f + (size_t)vol * NV + x * 4096u;   // contiguous (y,z) plane
    int t = threadIdx.x;
    {
        const float4* g4 = (const float4*)g;
#pragma unroll
        for (int m = 0; m < 4; ++m) {
            int e4 = m * 256 + t;            // 1024 float4s
            float4 val = g4[e4];
            int e = e4 * 4;
            int y = e >> 6, z = e & 63;
            float* sp = s + y * 65 + z;
            sp[0] = val.x; sp[1] = val.y; sp[2] = val.z; sp[3] = val.w;
        }
    }
    __syncthreads();
    pass_line<65, 1>(s, t);   // Y pass
    pass_line<1, 65>(s, t);   // Z pass
    {
        float4* g4 = (float4*)g;
#pragma unroll
        for (int m = 0; m < 4; ++m) {
            int e4 = m * 256 + t;
            int e = e4 * 4;
            int y = e >> 6, z = e & 63;
            const float* sp = s + y * 65 + z;
            float4 val;
            val.x = sp[0]; val.y = sp[1]; val.z = sp[2]; val.w = sp[3];
            g4[e4] = val;
        }
    }
}

// ---------------- windowed min-plus over channel axis, length 8, exact ----------------
__device__ __forceinline__ void minplus8w(const float* __restrict__ a, float* __restrict__ d) {
#pragma unroll
    for (int i = 0; i < 8; ++i) {
        float m = 3.0e38f;
#pragma unroll
        for (int j = 0; j < 8; ++j) {
            const int off = i - j;
            if (off * off <= 4) m = fminf(m, a[j] + (float)(off * off));
        }
        d[i] = m;
    }
    float mx = d[0];
#pragma unroll
    for (int i = 1; i < 8; ++i) mx = fmaxf(mx, d[i]);
    if (mx > 9.0f) {
#pragma unroll
        for (int i = 0; i < 8; ++i) {
            float m = d[i];
#pragma unroll
            for (int j = 0; j < 8; ++j) {
                const int off = i - j;
                m = fminf(m, a[j] + (float)(off * off));
            }
            d[i] = m;
        }
    }
}

// ---------------- fused stats + HD (+ channel EDT pass) + final ----------------
// 512 blocks x 256 threads x 4 voxels = 524288 (b, voxel) entries
__global__ void __launch_bounds__(256) k_shd(const float* __restrict__ in, const int* __restrict__ tg,
                                             float* __restrict__ out) {
    unsigned E = blockIdx.x * 1024u + threadIdx.x * 4u;
    unsigned v = E & (NV - 1u);
    unsigned b = E >> 18;

    float X[4][8];
#pragma unroll
    for (int c = 0; c < 8; ++c) {
        float4 t4 = *(const float4*)(in + (size_t)(b * 8 + c) * NV + v);
        X[0][c] = t4.x; X[1][c] = t4.y; X[2][c] = t4.z; X[3][c] = t4.w;
    }
    int T[4];
    { int4 tt = *(const int4*)(tg + (size_t)b * NV + v); T[0] = tt.x; T[1] = tt.y; T[2] = tt.z; T[3] = tt.w; }

    float tp[8], sP[8], cn[8];
#pragma unroll
    for (int c = 0; c < 8; ++c) { tp[c] = 0.f; sP[c] = 0.f; cn[c] = 0.f; }
    float ce = 0.0f, hd = 0.0f;

#pragma unroll
    for (int k = 0; k < 4; ++k) {
        float m = X[k][0];
#pragma unroll
        for (int c = 1; c < 8; ++c) m = fmaxf(m, X[k][c]);
        float e[8]; float S = 0.f;
#pragma unroll
        for (int c = 0; c < 8; ++c) { e[c] = exp2f((X[k][c] - m) * 1.4426950408889634f); S += e[c]; }
        float r = 1.0f / S;
        int t = T[k];
        float xt = X[k][0];
#pragma unroll
        for (int c = 0; c < 8; ++c) {
            float pr = e[c] * r;
            sP[c] += pr;
            bool is = (c == t);
            tp[c] += is ? pr : 0.0f;
            cn[c] += is ? 1.0f : 0.0f;
            xt     = is ? X[k][c] : xt;
        }
        ce += (m - xt) + __log2f(S) * 0.69314718055994531f;
    }

    // HD: per mask, channel-axis min-plus then weighted accumulate.
    // pred_dt^2 = d_fg + d_bg exactly (one of the pair is 0 at every voxel).
#pragma unroll
    for (int mk = 0; mk < 4; ++mk) {
        float A[4][8];
#pragma unroll
        for (int c = 0; c < 8; ++c) {
            float4 t4 = *(const float4*)(g_f + (size_t)(mk * 16 + b * 8 + c) * NV + v);
            A[0][c] = t4.x; A[1][c] = t4.y; A[2][c] = t4.z; A[3][c] = t4.w;
        }
#pragma unroll
        for (int k = 0; k < 4; ++k) {
            float dch[8];
            minplus8w(A[k], dch);
            int t = T[k];
#pragma unroll
            for (int c = 0; c < 8; ++c) {
                float toh = (t == c) ? 1.0f : 0.0f;
                float pe = X[k][c] - toh;
                hd += pe * pe * dch[c];
            }
        }
    }

#pragma unroll
    for (int c = 0; c < 8; ++c) {
        float a  = warpsum(tp[c]);
        float s2 = warpsum(sP[c]);
        float q  = warpsum(cn[c]);
        if ((threadIdx.x & 31) == 0) {
            atomicAdd(&g_acc[b * 8 + c], a);
            atomicAdd(&g_acc[16 + b * 8 + c], s2);
            atomicAdd(&g_acc[32 + b * 8 + c], q);
        }
    }
    float cs = warpsum(ce);
    float hs = warpsum(hd);
    if ((threadIdx.x & 31) == 0) {
        atomicAdd(&g_acc[48], cs);
        atomicAdd(&g_acc[49], hs);
    }

    // last block finalizes (threadfence + completion counter)
    __threadfence();
    if (threadIdx.x == 0) {
        unsigned done = atomicAdd(&g_cnt, 1u);
        if (done == gridDim.x - 1) {
            __threadfence();
            float diceAcc = 0.0f;
#pragma unroll
            for (int c = 1; c < 8; ++c) {
                float sb = 0.0f;
#pragma unroll
                for (int bb = 0; bb < 2; ++bb) {
                    float tps = g_acc[bb * 8 + c];
                    float sp  = g_acc[16 + bb * 8 + c];
                    float cnt = g_acc[32 + bb * 8 + c];
                    sb += 2.0f * tps / (sp + cnt + 1e-5f);   // alpha=beta=1
                }
                diceAcc += 0.5f * sb;
            }
            float dice = 1.0f - diceAcc * (1.0f / 7.0f);
            float cef = g_acc[48] * (1.0f / 524288.0f);
            float hdf = g_acc[49] * (1.0f / 4194304.0f);
            out[0] = dice + cef + hdf;
        }
    }
}

extern "C" void kernel_launch(void* const* d_in, const int* in_sizes, int n_in,
                              void* d_out, int out_size) {
    const float* in = (const float*)d_in[0];
    const int*   tg = (const int*)d_in[1];
    float* out = (float*)d_out;
    k_pass1 <<<1024, 256>>>(in, tg);
    k_pass23<<<4096, 256>>>();
    k_shd   <<<512, 256>>>(in, tg, out);
}

// round 7
// speedup vs baseline: 3.1282x; 1.5313x over previous
#include <cuda_runtime.h>

#define NV 262144            // 64*64*64
#define BIGF 1e9f

// scratch: [mask m (4)][bc (16)][voxel (NV)]  -> 67 MB
__device__ float g_f[64ull * NV];
__device__ float g_acc[64];
__device__ unsigned g_cnt;

__device__ __forceinline__ float warpsum(float v) {
#pragma unroll
    for (int o = 16; o > 0; o >>= 1) v += __shfl_xor_sync(0xffffffffu, v, o);
    return v;
}

// ---------------- pass 1 (axis X): binary -> squared dist to nearest False ----------------
__device__ __forceinline__ float dt1(unsigned long long zeros, int x) {
    unsigned long long below = zeros << (63 - x);      // bits <= x
    int dfwd = below ? __clzll((long long)below) : 1000;
    unsigned long long above = zeros >> x;             // bits >= x
    int dbwd = above ? (__ffsll((long long)above) - 1) : 1000;
    int d = min(dfwd, dbwd);
    return (d > 63) ? BIGF : (float)(d * d);
}

// 1024 blocks x 256 threads. Block = one (b,c,y) group of 64 z-lines.
// Each line is split over 4 threads (part = tid>>6): 16 loads each, partial
// masks combined via smem; then each part writes ONE mask's 64 outputs.
__global__ void __launch_bounds__(256) k_pass1(const float* __restrict__ in, const int* __restrict__ tg) {
    if (blockIdx.x == 0) {       // reset accumulators for this replay
        if (threadIdx.x < 64) g_acc[threadIdx.x] = 0.0f;
        if (threadIdx.x == 64) g_cnt = 0u;
    }
    unsigned g = blockIdx.x;                 // (b,c,y)
    unsigned y = g & 63u, c = (g >> 6) & 7u, b = g >> 9;
    unsigned bc = b * 8u + c;
    int t = threadIdx.x;
    int z = t & 63;
    int part = t >> 6;                       // 0..3
    const float* pin = in + (size_t)bc * NV + y * 64u + z;
    const int*   ptg = tg + (size_t)b  * NV + y * 64u + z;

    unsigned m16 = 0u;                       // low 16: pred, high 16: tgt
#pragma unroll
    for (int k = 0; k < 16; ++k) {
        int x = part * 16 + k;
        float v = pin[(size_t)x * 4096];
        int   tt = ptg[(size_t)x * 4096];
        if (v > 0.5f)          m16 |= 1u << k;
        if ((unsigned)tt == c) m16 |= 1u << (16 + k);
    }
    __shared__ unsigned sm[256];
    sm[t] = m16;
    __syncthreads();
    unsigned long long mP = 0ull, mT = 0ull;
#pragma unroll
    for (int p = 0; p < 4; ++p) {
        unsigned w = sm[z + p * 64];
        mP |= (unsigned long long)(w & 0xFFFFu) << (16 * p);
        mT |= (unsigned long long)(w >> 16)     << (16 * p);
    }
    // mask order: 0=pred_fg, 1=tgt_fg, 2=pred_bg, 3=tgt_bg ; zeros-of-mask
    unsigned long long zeros = (part == 0) ? ~mP : (part == 1) ? ~mT : (part == 2) ? mP : mT;
    float* o = g_f + (size_t)(part * 16 + bc) * NV + y * 64u + z;
#pragma unroll 4
    for (int x = 0; x < 64; ++x) o[(size_t)x * 4096] = dt1(zeros, x);
}

// ---------------- fused Y+Z min-plus over one (y,z) plane in smem ----------------
// Exact: windowed min, pairs |i-j|<=3 (off^2<=9). If windowed min <= 16 it is
// the true min (outside pairs contribute >= 16); otherwise full-scan fallback.
template<int LSTRIDE, int LANESTRIDE>
__device__ __forceinline__ void pass_line(float* s, int t) {
    int lane = t & 63;           // orthogonal coordinate
    int h = t >> 6;              // 0..3 -> outputs i in [16h, 16h+16)
    float* bp = s + lane * LANESTRIDE;
    int jbase = 16 * h - 3;
    float fv[22];
#pragma unroll
    for (int k = 0; k < 22; ++k) {
        int j = jbase + k;
        fv[k] = (j >= 0 && j < 64) ? bp[j * LSTRIDE] : 3.0e38f;
    }
    float d[16];
#pragma unroll
    for (int a = 0; a < 16; ++a) d[a] = 3.0e38f;
    // chunk A: a=0..7 (i=16h+a), off = a+3-k
#pragma unroll
    for (int k = 0; k < 14; ++k) {
#pragma unroll
        for (int a = 0; a < 8; ++a) {
            const int off = a + 3 - k;
            if (off * off <= 9) d[a] = fminf(d[a], fv[k] + (float)(off * off));
        }
    }
    // chunk B: a=8..15
#pragma unroll
    for (int k = 8; k < 22; ++k) {
#pragma unroll
        for (int a = 8; a < 16; ++a) {
            const int off = a + 3 - k;
            if (off * off <= 9) d[a] = fminf(d[a], fv[k] + (float)(off * off));
        }
    }
    float mxA = d[0], mxB = d[8];
#pragma unroll
    for (int a = 1; a < 8; ++a) { mxA = fmaxf(mxA, d[a]); mxB = fmaxf(mxB, d[a + 8]); }
    if (mxA > 16.0f) {
#pragma unroll 1
        for (int j = 0; j < 64; ++j) {
            float fj = bp[j * LSTRIDE];
#pragma unroll
            for (int a = 0; a < 8; ++a) { int dd = 16 * h + a - j; d[a] = fminf(d[a], fj + (float)(dd * dd)); }
        }
    }
    if (mxB > 16.0f) {
#pragma unroll 1
        for (int j = 0; j < 64; ++j) {
            float fj = bp[j * LSTRIDE];
#pragma unroll
            for (int a = 8; a < 16; ++a) { int dd = 16 * h + a - j; d[a] = fminf(d[a], fj + (float)(dd * dd)); }
        }
    }
    __syncthreads();   // all reads (incl. fallback) done before anyone writes
#pragma unroll
    for (int a = 0; a < 16; ++a) bp[(16 * h + a) * LSTRIDE] = d[a];
    __syncthreads();
}

__global__ void __launch_bounds__(256) k_pass23() {
    __shared__ float s[64 * 65];
    unsigned vol = blockIdx.x >> 6, x = blockIdx.x & 63u;
    float* g = g_f + (size_t)vol * NV + x * 4096u;   // contiguous (y,z) plane
    int t = threadIdx.x;
    {
        const float4* g4 = (const float4*)g;
#pragma unroll
        for (int m = 0; m < 4; ++m) {
            int e4 = m * 256 + t;            // 1024 float4s
            float4 val = g4[e4];
            int e = e4 * 4;
            int y = e >> 6, z = e & 63;
            float* sp = s + y * 65 + z;
            sp[0] = val.x; sp[1] = val.y; sp[2] = val.z; sp[3] = val.w;
        }
    }
    __syncthreads();
    pass_line<65, 1>(s, t);   // Y pass
    pass_line<1, 65>(s, t);   // Z pass
    {
        float4* g4 = (float4*)g;
#pragma unroll
        for (int m = 0; m < 4; ++m) {
            int e4 = m * 256 + t;
            int e = e4 * 4;
            int y = e >> 6, z = e & 63;
            const float* sp = s + y * 65 + z;
            float4 val;
            val.x = sp[0]; val.y = sp[1]; val.z = sp[2]; val.w = sp[3];
            g4[e4] = val;
        }
    }
}

// ---------------- full min-plus over channel axis, length 8, branchless ----------------
__device__ __forceinline__ void minplus8(const float* __restrict__ a, float* __restrict__ d) {
#pragma unroll
    for (int i = 0; i < 8; ++i) {
        float m = 3.0e38f;
#pragma unroll
        for (int j = 0; j < 8; ++j) {
            const float q = (float)((i - j) * (i - j));
            m = fminf(m, a[j] + q);
        }
        d[i] = m;
    }
}

// ---------------- fused stats + HD (+ channel EDT pass) + final ----------------
// 1024 blocks x 256 threads x 2 voxels = 524288 (b, voxel) entries
__global__ void __launch_bounds__(256) k_shd(const float* __restrict__ in, const int* __restrict__ tg,
                                             float* __restrict__ out) {
    unsigned E = (blockIdx.x * 256u + threadIdx.x) * 2u;
    unsigned v = E & (NV - 1u);
    unsigned b = E >> 18;

    float X[2][8];
#pragma unroll
    for (int c = 0; c < 8; ++c) {
        float2 t2 = *(const float2*)(in + (size_t)(b * 8 + c) * NV + v);
        X[0][c] = t2.x; X[1][c] = t2.y;
    }
    int T[2];
    { int2 tt = *(const int2*)(tg + (size_t)b * NV + v); T[0] = tt.x; T[1] = tt.y; }

    float tp[8], sP[8], cn[8];
#pragma unroll
    for (int c = 0; c < 8; ++c) { tp[c] = 0.f; sP[c] = 0.f; cn[c] = 0.f; }
    float ce = 0.0f, hd = 0.0f;

#pragma unroll
    for (int k = 0; k < 2; ++k) {
        float m = X[k][0];
#pragma unroll
        for (int c = 1; c < 8; ++c) m = fmaxf(m, X[k][c]);
        float e[8]; float S = 0.f;
#pragma unroll
        for (int c = 0; c < 8; ++c) { e[c] = exp2f((X[k][c] - m) * 1.4426950408889634f); S += e[c]; }
        float r = 1.0f / S;
        int t = T[k];
        float xt = X[k][0];
#pragma unroll
        for (int c = 0; c < 8; ++c) {
            float pr = e[c] * r;
            sP[c] += pr;
            bool is = (c == t);
            tp[c] += is ? pr : 0.0f;
            cn[c] += is ? 1.0f : 0.0f;
            xt     = is ? X[k][c] : xt;
        }
        ce += (m - xt) + __log2f(S) * 0.69314718055994531f;
    }

    // HD: per mask, full channel-axis min-plus (branchless, exact) then accumulate.
    // pred_dt^2 = d_fg + d_bg exactly (one of the pair is 0 at every voxel).
#pragma unroll
    for (int mk = 0; mk < 4; ++mk) {
        float A[2][8];
#pragma unroll
        for (int c = 0; c < 8; ++c) {
            float2 t2 = *(const float2*)(g_f + (size_t)(mk * 16 + b * 8 + c) * NV + v);
            A[0][c] = t2.x; A[1][c] = t2.y;
        }
#pragma unroll
        for (int k = 0; k < 2; ++k) {
            float dch[8];
            minplus8(A[k], dch);
            int t = T[k];
#pragma unroll
            for (int c = 0; c < 8; ++c) {
                float toh = (t == c) ? 1.0f : 0.0f;
                float pe = X[k][c] - toh;
                hd += pe * pe * dch[c];
            }
        }
    }

    // warp reduce 26 scalars, then block-stage in smem, then 26 atomics per block
    __shared__ float sred[26 * 8];
    int w = threadIdx.x >> 5;
#pragma unroll
    for (int c = 0; c < 8; ++c) {
        float a  = warpsum(tp[c]);
        float s2 = warpsum(sP[c]);
        float q  = warpsum(cn[c]);
        if ((threadIdx.x & 31) == 0) {
            sred[c * 8 + w]        = a;
            sred[(8 + c) * 8 + w]  = s2;
            sred[(16 + c) * 8 + w] = q;
        }
    }
    float cs = warpsum(ce);
    float hs = warpsum(hd);
    if ((threadIdx.x & 31) == 0) { sred[24 * 8 + w] = cs; sred[25 * 8 + w] = hs; }
    __syncthreads();
    if (threadIdx.x < 26) {
        int i = threadIdx.x;
        float s = 0.f;
#pragma unroll
        for (int ww = 0; ww < 8; ++ww) s += sred[i * 8 + ww];
        float* dst;
        if (i < 8)       dst = &g_acc[b * 8 + i];
        else if (i < 16) dst = &g_acc[16 + b * 8 + (i - 8)];
        else if (i < 24) dst = &g_acc[32 + b * 8 + (i - 16)];
        else if (i == 24) dst = &g_acc[48];
        else              dst = &g_acc[49];
        atomicAdd(dst, s);
    }

    // last block finalizes (threadfence + completion counter)
    __threadfence();
    __syncthreads();
    if (threadIdx.x == 0) {
        unsigned done = atomicAdd(&g_cnt, 1u);
        if (done == gridDim.x - 1) {
            __threadfence();
            float diceAcc = 0.0f;
#pragma unroll
            for (int c = 1; c < 8; ++c) {
                float sb = 0.0f;
#pragma unroll
                for (int bb = 0; bb < 2; ++bb) {
                    float tps = g_acc[bb * 8 + c];
                    float sp  = g_acc[16 + bb * 8 + c];
                    float cnt = g_acc[32 + bb * 8 + c];
                    sb += 2.0f * tps / (sp + cnt + 1e-5f);   // alpha=beta=1
                }
                diceAcc += 0.5f * sb;
            }
            float dice = 1.0f - diceAcc * (1.0f / 7.0f);
            float cef = g_acc[48] * (1.0f / 524288.0f);
            float hdf = g_acc[49] * (1.0f / 4194304.0f);
            out[0] = dice + cef + hdf;
        }
    }
}

extern "C" void kernel_launch(void* const* d_in, const int* in_sizes, int n_in,
                              void* d_out, int out_size) {
    const float* in = (const float*)d_in[0];
    const int*   tg = (const int*)d_in[1];
    float* out = (float*)d_out;
    k_pass1 <<<1024, 256>>>(in, tg);
    k_pass23<<<4096, 256>>>();
    k_shd   <<<1024, 256>>>(in, tg, out);
}